// round 2
// baseline (speedup 1.0000x reference)
#include <cuda_runtime.h>
#include <math.h>

#define FDIM 128
#define HDIM 32
#define NN_MAX 100000
#define NGRAPH 512

// Scratch (no allocation allowed)
__device__ __align__(128) float g_h[NN_MAX * HDIM];
__device__ __align__(128) float g_acc[NN_MAX * HDIM];
__device__ __align__(128) float g_pool[NGRAPH * HDIM];

// ---------------------------------------------------------------------------
// GEMM1: h = x @ W1   ([N,128] @ [128,32])
// Block: 256 threads = 8 warps; each warp computes one node row (32 outputs).
// W1 cached in smem once per block; block loops over node groups (grid-stride).
// ---------------------------------------------------------------------------
__global__ void gemm1_kernel(const float* __restrict__ x,
                             const float* __restrict__ W,
                             float* __restrict__ h, int N) {
    __shared__ float sW[FDIM * HDIM];   // 16 KB
    __shared__ float sx[8 * FDIM];      // 4 KB
    int tid = threadIdx.x;
    for (int i = tid; i < FDIM * HDIM; i += blockDim.x) sW[i] = W[i];
    int warp = tid >> 5, lane = tid & 31;

    for (long base = (long)blockIdx.x * 8; base < N; base += (long)gridDim.x * 8) {
        int nrows = (int)min((long)8, (long)N - base);
        __syncthreads();
        // cooperative vectorized load of up to 8 node rows
        int nquads = nrows * (FDIM / 4);
        const float4* src = (const float4*)(x + base * FDIM);
        for (int i = tid; i < nquads; i += blockDim.x)
            ((float4*)sx)[i] = src[i];
        __syncthreads();
        if (warp < nrows) {
            const float* xr = sx + warp * FDIM;
            float acc = 0.f;
#pragma unroll 16
            for (int k = 0; k < FDIM; k++)
                acc += xr[k] * sW[k * HDIM + lane];
            h[(base + warp) * HDIM + lane] = acc;
        }
    }
}

// ---------------------------------------------------------------------------
// Fused  h_out = (elu(acc + b)) @ W   ([N,32] @ [32,32])
// Warp per node: lane holds elu(acc[n][lane]+b[lane]); shuffle-broadcast GEMM.
// ---------------------------------------------------------------------------
__global__ void gemm_elu_kernel(const float* __restrict__ acc_in,
                                const float* __restrict__ b,
                                const float* __restrict__ W,
                                float* __restrict__ h, int N) {
    __shared__ float sW[HDIM * HDIM];
    __shared__ float sb[HDIM];
    int tid = threadIdx.x;
    for (int i = tid; i < HDIM * HDIM; i += blockDim.x) sW[i] = W[i];
    if (tid < HDIM) sb[tid] = b[tid];
    __syncthreads();

    int lane = tid & 31;
    int gwarp = (blockIdx.x * blockDim.x + tid) >> 5;
    int nwarps = (gridDim.x * blockDim.x) >> 5;
    for (int n = gwarp; n < N; n += nwarps) {
        float v = acc_in[n * HDIM + lane] + sb[lane];
        v = v > 0.f ? v : (expf(v) - 1.f);     // ELU (alpha=1)
        float o = 0.f;
#pragma unroll
        for (int k = 0; k < HDIM; k++)
            o += __shfl_sync(0xffffffffu, v, k) * sW[k * HDIM + lane];
        h[n * HDIM + lane] = o;
    }
}

// ---------------------------------------------------------------------------
// SpMM: acc[row] += w * h[col]   (32-wide rows)
// 8 threads per edge; float4 gather + red.global.add.v4.f32 scatter.
// ---------------------------------------------------------------------------
__global__ void spmm_kernel(const int* __restrict__ row,
                            const int* __restrict__ col,
                            const float* __restrict__ w,
                            const float* __restrict__ h,
                            float* __restrict__ acc, int E) {
    int t = blockIdx.x * blockDim.x + threadIdx.x;
    int e = t >> 3;
    if (e >= E) return;
    int l = t & 7;
    int r = row[e];
    int c = col[e];
    float wt = w[e];
    float4 v = ((const float4*)(h + (long)c * HDIM))[l];
    v.x *= wt; v.y *= wt; v.z *= wt; v.w *= wt;
    float4* dst = ((float4*)(acc + (long)r * HDIM)) + l;
    asm volatile("red.global.add.v4.f32 [%0], {%1,%2,%3,%4};"
                 :: "l"(__cvta_generic_to_global(dst)),
                    "f"(v.x), "f"(v.y), "f"(v.z), "f"(v.w)
                 : "memory");
}

// ---------------------------------------------------------------------------
// Pool: pool[seg[n]][c] += elu(acc[n][c] + b[c])
// ---------------------------------------------------------------------------
__global__ void pool_kernel(const float* __restrict__ acc,
                            const float* __restrict__ b,
                            const int* __restrict__ seg,
                            float* __restrict__ pool, int N) {
    int idx = blockIdx.x * blockDim.x + threadIdx.x;
    if (idx >= N * HDIM) return;
    int n = idx >> 5, c = idx & 31;
    float v = acc[idx] + b[c];
    v = v > 0.f ? v : (expf(v) - 1.f);
    atomicAdd(&pool[seg[n] * HDIM + c], v);   // ptxas -> REDG (no return)
}

// ---------------------------------------------------------------------------
// MLP head: out = sigmoid(relu(relu(pool@Wd1+bd1)@Wd2+bd2)@Wd3+bd3)
// One thread per graph.
// ---------------------------------------------------------------------------
__global__ void mlp_kernel(const float* __restrict__ pool,
                           const float* __restrict__ W1, const float* __restrict__ b1,
                           const float* __restrict__ W2, const float* __restrict__ b2,
                           const float* __restrict__ W3, const float* __restrict__ b3,
                           float* __restrict__ out) {
    __shared__ float sW1[32 * 64], sW2[64 * 32], sW3[32], sb1[64], sb2[32];
    int tid = threadIdx.x;
    for (int i = tid; i < 2048; i += blockDim.x) { sW1[i] = W1[i]; sW2[i] = W2[i]; }
    if (tid < 64) sb1[tid] = b1[tid];
    if (tid < 32) { sW3[tid] = W3[tid]; sb2[tid] = b2[tid]; }
    __syncthreads();

    int g = blockIdx.x * blockDim.x + tid;
    if (g >= NGRAPH) return;
    float in[32];
#pragma unroll
    for (int c = 0; c < 32; c++) in[c] = pool[g * 32 + c];
    float h2[32];
#pragma unroll
    for (int c = 0; c < 32; c++) h2[c] = sb2[c];
    for (int j = 0; j < 64; j++) {
        float t = sb1[j];
#pragma unroll
        for (int c = 0; c < 32; c++) t += in[c] * sW1[c * 64 + j];
        t = fmaxf(t, 0.f);
#pragma unroll
        for (int c = 0; c < 32; c++) h2[c] += t * sW2[j * 32 + c];
    }
    float o = b3[0];
#pragma unroll
    for (int c = 0; c < 32; c++) o += fmaxf(h2[c], 0.f) * sW3[c];
    out[g] = 1.f / (1.f + expf(-o));
}

// ---------------------------------------------------------------------------
extern "C" void kernel_launch(void* const* d_in, const int* in_sizes, int n_in,
                              void* d_out, int out_size) {
    const float* x   = (const float*)d_in[0];
    const int*   ei  = (const int*)  d_in[1];
    const float* ew  = (const float*)d_in[2];
    const int*   seg = (const int*)  d_in[3];
    const float* W1  = (const float*)d_in[4];
    const float* b1  = (const float*)d_in[5];
    const float* W2  = (const float*)d_in[6];
    const float* b2  = (const float*)d_in[7];
    const float* W3  = (const float*)d_in[8];
    const float* b3  = (const float*)d_in[9];
    const float* Wd1 = (const float*)d_in[10];
    const float* bd1 = (const float*)d_in[11];
    const float* Wd2 = (const float*)d_in[12];
    const float* bd2 = (const float*)d_in[13];
    const float* Wd3 = (const float*)d_in[14];
    const float* bd3 = (const float*)d_in[15];
    float* out = (float*)d_out;

    int N = in_sizes[0] / FDIM;
    int E = in_sizes[1] / 2;
    const int* row = ei;
    const int* col = ei + E;

    float *h, *acc, *pool;
    cudaGetSymbolAddress((void**)&h,    g_h);
    cudaGetSymbolAddress((void**)&acc,  g_acc);
    cudaGetSymbolAddress((void**)&pool, g_pool);

    size_t accBytes = (size_t)N * HDIM * sizeof(float);
    int spmmBlocks = (E * 8 + 255) / 256;

    // Layer 1
    gemm1_kernel<<<1480, 256>>>(x, W1, h, N);
    cudaMemsetAsync(acc, 0, accBytes);
    spmm_kernel<<<spmmBlocks, 256>>>(row, col, ew, h, acc, E);

    // Layer 2 (fuses layer-1 bias+ELU)
    gemm_elu_kernel<<<1480, 256>>>(acc, b1, W2, h, N);
    cudaMemsetAsync(acc, 0, accBytes);
    spmm_kernel<<<spmmBlocks, 256>>>(row, col, ew, h, acc, E);

    // Layer 3 (fuses layer-2 bias+ELU)
    gemm_elu_kernel<<<1480, 256>>>(acc, b2, W3, h, N);
    cudaMemsetAsync(acc, 0, accBytes);
    spmm_kernel<<<spmmBlocks, 256>>>(row, col, ew, h, acc, E);

    // Pool (fuses layer-3 bias+ELU) + MLP head
    cudaMemsetAsync(pool, 0, (size_t)NGRAPH * HDIM * sizeof(float));
    pool_kernel<<<(N * HDIM + 255) / 256, 256>>>(acc, b3, seg, pool, N);
    mlp_kernel<<<2, 256>>>(pool, Wd1, bd1, Wd2, bd2, Wd3, bd3, out);
}